// round 12
// baseline (speedup 1.0000x reference)
#include <cuda_runtime.h>
#include <cuda_fp16.h>
#include <cstdint>
#include <cstring>

// GTN collapses (softmax over singleton axis == 1 -> gtconv == 2*A):
//   H   = 4*(A@A) + I
//   inv = 2 / rowsum(H)   (guarded)
//   out = diag(inv) @ (H @ A)
// EXPERIMENT: f16 inputs + f16-accumulate HMMA (testing double-rate vs the
// fp32-acc 52.6% tensor-active plateau), with fp32 spill every 2 k-tiles.
// H stored as H/64 in f16 (avoids f16 chunk overflow), rescaled in epilogue.

#define NMAT 2048
static constexpr int BM = 256;
static constexpr int BN = 128;
static constexpr int BK = 32;
static constexpr int STAGES = 4;
static constexpr int KT = NMAT / BK;             // 64
static constexpr int A_STAGE = BM * 64;          // 16KB (64B rows, M-major)
static constexpr int B_STAGE = BK * 256;         // 8KB  (256B k-rows)
static constexpr int SMEM_B_OFF = STAGES * A_STAGE;
static constexpr int SMEM_DYN = STAGES * (A_STAGE + B_STAGE);  // 96KB

static constexpr float H_SCALE = 1.0f / 64.0f;   // g_Hh stores H/64

__device__ __half g_Ah[(size_t)NMAT * NMAT];
__device__ __half g_Hh[(size_t)NMAT * NMAT];
__device__ float g_rowpart[4][NMAT / BN][NMAT];

__device__ __forceinline__ uint32_t smem_u32(const void* p) {
    uint32_t a;
    asm("{ .reg .u64 t; cvta.to.shared.u64 t, %1; cvt.u32.u64 %0, t; }" : "=r"(a) : "l"(p));
    return a;
}
#define CP_ASYNC16(dst, src) asm volatile("cp.async.cg.shared.global [%0], [%1], 16;" :: "r"(dst), "l"(src) : "memory")
#define CP_COMMIT()          asm volatile("cp.async.commit_group;" ::: "memory")
#define CP_WAIT2()           asm volatile("cp.async.wait_group 2;" ::: "memory")
#define LDSM_X4(r0, r1, r2, r3, a) \
    asm volatile("ldmatrix.sync.aligned.m8n8.x4.shared.b16 {%0,%1,%2,%3}, [%4];" \
                 : "=r"(r0), "=r"(r1), "=r"(r2), "=r"(r3) : "r"(a))
#define LDSM_X4T(r0, r1, r2, r3, a) \
    asm volatile("ldmatrix.sync.aligned.m8n8.x4.trans.shared.b16 {%0,%1,%2,%3}, [%4];" \
                 : "=r"(r0), "=r"(r1), "=r"(r2), "=r"(r3) : "r"(a))
// f16 x f16 -> f16 accumulate: D/C are 2 regs (packed half2: (c0,c1) row r, row r+8)
#define MMA_F16ACC(c0, c1, a, b) \
    asm volatile("mma.sync.aligned.m16n8k16.row.col.f16.f16.f16.f16 " \
                 "{%0,%1}, {%2,%3,%4,%5}, {%6,%7}, {%0,%1};" \
                 : "+r"(c0), "+r"(c1) \
                 : "r"((a)[0]), "r"((a)[1]), "r"((a)[2]), "r"((a)[3]), "r"((b)[0]), "r"((b)[1]))

__device__ __forceinline__ uint32_t swzA(int row, int colb) {
    return (uint32_t)(row * 64 + (colb ^ (((row >> 1) & 3) << 4)));
}
__device__ __forceinline__ uint32_t swzB(int k, int chunk) {
    return (uint32_t)(k * 256 + ((chunk ^ (k & 7)) << 4));
}
__device__ __forceinline__ uint32_t h2_bits(__half2 v) {
    uint32_t u; memcpy(&u, &v, 4); return u;
}
__device__ __forceinline__ float2 bits_f2(uint32_t u) {
    __half2 h; memcpy(&h, &u, 4); return __half22float2(h);
}

// ---------------- A -> f16 (streaming, coalesced) ----------------
__global__ void convert_kernel(const float* __restrict__ A)
{
    const float4* __restrict__ A4 = reinterpret_cast<const float4*>(A);
    uint2* __restrict__ O2 = reinterpret_cast<uint2*>(g_Ah);
    const int base = blockIdx.x * 1024 + threadIdx.x;
    float4 v[4];
#pragma unroll
    for (int i = 0; i < 4; i++) v[i] = A4[base + i * 256];
#pragma unroll
    for (int i = 0; i < 4; i++) {
        uint2 o;
        o.x = h2_bits(__floats2half2_rn(v[i].x, v[i].y));
        o.y = h2_bits(__floats2half2_rn(v[i].z, v[i].w));
        O2[base + i * 256] = o;
    }
}

// ---------------- HMMA GEMM, CTA 256x128, warp 64x32, f16-acc + fp32 spill -------
// MODE 0: L = g_Ah ; H = 4D + I -> g_Hh (stored /64) + fp32 row partials
// MODE 1: L = g_Hh (H/64) ; out = s_inv[r] * 64 * D
template <int MODE>
__launch_bounds__(512, 1)
__global__ void gemm_mma(float* __restrict__ Cout)
{
    extern __shared__ char dyn_raw[];
    const uint32_t sb = smem_u32(dyn_raw);
    __shared__ float s_inv[BM];

    const int tid = threadIdx.x;
    const int lane = tid & 31;
    const int wid = tid >> 5;
    const int warp_m = wid & 3;
    const int warp_n = wid >> 2;
    const int row0 = blockIdx.y * BM;
    const int col0 = blockIdx.x * BN;

    const __half* __restrict__ Lop = (MODE == 0) ? g_Ah : g_Hh;
    const __half* __restrict__ Rop = g_Ah;

    uint32_t abase[2];
#pragma unroll
    for (int st = 0; st < 2; st++)
        abase[st] = swzA(warp_m * 64 + (lane & 15), st * 32 + ((lane >> 4) << 4));

    uint32_t bbase[2][2];
    {
        const int m = lane >> 3, r = lane & 7;
#pragma unroll
        for (int st = 0; st < 2; st++)
#pragma unroll
            for (int np = 0; np < 2; np++)
                bbase[st][np] = swzB(st * 16 + ((m & 1) << 3) + r,
                                     warp_n * 4 + np * 2 + (m >> 1));
    }

    auto fill = [&](int kt, int s) {
        const uint32_t ab = sb + s * A_STAGE;
        const uint32_t bb = sb + SMEM_B_OFF + s * B_STAGE;
#pragma unroll
        for (int i = 0; i < 2; i++) {
            const int ch = i * 512 + tid;
            const int row = ch >> 2, c16 = ch & 3;
            CP_ASYNC16(ab + swzA(row, c16 * 16),
                       Lop + (size_t)(row0 + row) * NMAT + kt * BK + c16 * 8);
        }
        {
            const int krow = tid >> 4, c = tid & 15;
            CP_ASYNC16(bb + swzB(krow, c),
                       Rop + (size_t)(kt * BK + krow) * NMAT + col0 + c * 8);
        }
    };

    float facc[4][4][4];
#pragma unroll
    for (int mt = 0; mt < 4; mt++)
#pragma unroll
        for (int nt = 0; nt < 4; nt++)
#pragma unroll
            for (int j = 0; j < 4; j++) facc[mt][nt][j] = 0.f;
    uint32_t hacc[4][4][2];
#pragma unroll
    for (int mt = 0; mt < 4; mt++)
#pragma unroll
        for (int nt = 0; nt < 4; nt++) { hacc[mt][nt][0] = 0u; hacc[mt][nt][1] = 0u; }

    fill(0, 0); CP_COMMIT();
    fill(1, 1); CP_COMMIT();
    fill(2, 2); CP_COMMIT();

    if (MODE == 1 && tid < BM) {
        const int r = row0 + tid;
        float d = 0.f;
#pragma unroll
        for (int h = 0; h < 4; h++)
#pragma unroll
            for (int t = 0; t < NMAT / BN; t++) d += g_rowpart[h][t][r];
        if (d <= 1e-10f) d = 1.f;
        s_inv[tid] = 2.f / d;
    }

    for (int kt = 0; kt < KT; kt++) {
        CP_WAIT2();
        __syncthreads();
        const int s = kt & (STAGES - 1);
        const uint32_t ab = sb + s * A_STAGE;
        const uint32_t bb = sb + SMEM_B_OFF + s * B_STAGE;

        uint32_t a[4][4], b[2][4];

        // ---- step 0 ----
#pragma unroll
        for (int mt = 0; mt < 4; mt++)
            LDSM_X4(a[mt][0], a[mt][1], a[mt][2], a[mt][3], ab + abase[0] + mt * 1024);
#pragma unroll
        for (int np = 0; np < 2; np++)
            LDSM_X4T(b[np][0], b[np][1], b[np][2], b[np][3], bb + bbase[0][np]);

        const int f = kt + 3;
        if (f < KT) fill(f, f & (STAGES - 1));
        CP_COMMIT();

#pragma unroll
        for (int mt = 0; mt < 4; mt++)
#pragma unroll
            for (int nt = 0; nt < 4; nt++) {
                uint32_t bf[2] = {b[nt >> 1][(nt & 1) * 2], b[nt >> 1][(nt & 1) * 2 + 1]};
                MMA_F16ACC(hacc[mt][nt][0], hacc[mt][nt][1], a[mt], bf);
            }

        // ---- step 1 ----
#pragma unroll
        for (int mt = 0; mt < 4; mt++)
            LDSM_X4(a[mt][0], a[mt][1], a[mt][2], a[mt][3], ab + abase[1] + mt * 1024);
#pragma unroll
        for (int np = 0; np < 2; np++)
            LDSM_X4T(b[np][0], b[np][1], b[np][2], b[np][3], bb + bbase[1][np]);
#pragma unroll
        for (int mt = 0; mt < 4; mt++)
#pragma unroll
            for (int nt = 0; nt < 4; nt++) {
                uint32_t bf[2] = {b[nt >> 1][(nt & 1) * 2], b[nt >> 1][(nt & 1) * 2 + 1]};
                MMA_F16ACC(hacc[mt][nt][0], hacc[mt][nt][1], a[mt], bf);
            }

        // ---- spill f16 partials -> fp32 every 2 k-tiles ----
        if (kt & 1) {
#pragma unroll
            for (int mt = 0; mt < 4; mt++)
#pragma unroll
                for (int nt = 0; nt < 4; nt++) {
                    const float2 p0 = bits_f2(hacc[mt][nt][0]);
                    const float2 p1 = bits_f2(hacc[mt][nt][1]);
                    facc[mt][nt][0] += p0.x;
                    facc[mt][nt][1] += p0.y;
                    facc[mt][nt][2] += p1.x;
                    facc[mt][nt][3] += p1.y;
                    hacc[mt][nt][0] = 0u;
                    hacc[mt][nt][1] = 0u;
                }
        }
    }

    // ---------------- epilogue ----------------
#pragma unroll
    for (int mt = 0; mt < 4; mt++) {
        const int rA = row0 + warp_m * 64 + mt * 16 + (lane >> 2);
        const float s0 = (MODE == 0) ? 4.0f : s_inv[rA - row0] * 64.0f;
        const float s1 = (MODE == 0) ? 4.0f : s_inv[rA + 8 - row0] * 64.0f;
        float rs0 = 0.f, rs1 = 0.f;
#pragma unroll
        for (int nt = 0; nt < 4; nt++) {
            const int c = col0 + warp_n * 32 + nt * 8 + (lane & 3) * 2;
            float v0 = s0 * facc[mt][nt][0];
            float v1 = s0 * facc[mt][nt][1];
            float v2 = s1 * facc[mt][nt][2];
            float v3 = s1 * facc[mt][nt][3];
            if (MODE == 0) {
                if (rA == c)         v0 += 1.0f;
                if (rA == c + 1)     v1 += 1.0f;
                if (rA + 8 == c)     v2 += 1.0f;
                if (rA + 8 == c + 1) v3 += 1.0f;
                rs0 += v0 + v1;
                rs1 += v2 + v3;
                *reinterpret_cast<__half2*>(g_Hh + (size_t)rA * NMAT + c) =
                    __floats2half2_rn(v0 * H_SCALE, v1 * H_SCALE);
                *reinterpret_cast<__half2*>(g_Hh + (size_t)(rA + 8) * NMAT + c) =
                    __floats2half2_rn(v2 * H_SCALE, v3 * H_SCALE);
            } else {
                *reinterpret_cast<float2*>(Cout + (size_t)rA * NMAT + c) = make_float2(v0, v1);
                *reinterpret_cast<float2*>(Cout + (size_t)(rA + 8) * NMAT + c) = make_float2(v2, v3);
            }
        }
        if (MODE == 0) {
            rs0 += __shfl_xor_sync(0xFFFFFFFF, rs0, 1);
            rs0 += __shfl_xor_sync(0xFFFFFFFF, rs0, 2);
            rs1 += __shfl_xor_sync(0xFFFFFFFF, rs1, 1);
            rs1 += __shfl_xor_sync(0xFFFFFFFF, rs1, 2);
            if ((lane & 3) == 0) {
                g_rowpart[warp_n][blockIdx.x][rA] = rs0;
                g_rowpart[warp_n][blockIdx.x][rA + 8] = rs1;
            }
        }
    }
}

extern "C" void kernel_launch(void* const* d_in, const int* in_sizes, int n_in,
                              void* d_out, int out_size)
{
    const float* A = (const float*)d_in[0];   // weights unused: softmax over singleton == 1
    float* out = (float*)d_out;

    cudaFuncSetAttribute(gemm_mma<0>, cudaFuncAttributeMaxDynamicSharedMemorySize, SMEM_DYN);
    cudaFuncSetAttribute(gemm_mma<1>, cudaFuncAttributeMaxDynamicSharedMemorySize, SMEM_DYN);

    convert_kernel<<<NMAT * NMAT / 4096, 256>>>(A);
    gemm_mma<0><<<dim3(NMAT / BN, NMAT / BM), 512, SMEM_DYN>>>(out);   // H = 4*A@A + I (stored /64)
    gemm_mma<1><<<dim3(NMAT / BN, NMAT / BM), 512, SMEM_DYN>>>(out);   // out = diag(2/deg)@(H@A)
}

// round 13
// speedup vs baseline: 1.5119x; 1.5119x over previous
#include <cuda_runtime.h>
#include <cuda_bf16.h>
#include <cstdint>
#include <cstring>

// GTN collapses (softmax over singleton axis == 1 -> gtconv == 2*A):
//   H   = 4*(A@A) + I
//   inv = 2 / rowsum(H)   (guarded)
//   out = diag(inv) @ (H @ A)
// bf16 HMMA at its measured sm_103 mma.sync ceiling (~53us/GEMM; f16-acc
// double-rate theory falsified in R12). This round: single persistent kernel
// (convert -> barrier -> GEMM1 -> barrier -> GEMM2) with a self-resetting
// software grid barrier; 128 CTAs @ 96KB smem are all co-resident (1/SM).

#define NMAT 2048
static constexpr int BM = 256;
static constexpr int BN = 128;
static constexpr int BK = 32;
static constexpr int STAGES = 4;
static constexpr int KT = NMAT / BK;             // 64
static constexpr int A_STAGE = BM * 64;          // 16KB (64B rows, M-major)
static constexpr int B_STAGE = BK * 256;         // 8KB  (256B k-rows)
static constexpr int SMEM_B_OFF = STAGES * A_STAGE;
static constexpr int SMEM_DYN = STAGES * (A_STAGE + B_STAGE);  // 96KB
static constexpr int NCTA = (NMAT / BN) * (NMAT / BM);         // 128

__device__ __nv_bfloat16 g_Abf[(size_t)NMAT * NMAT];
__device__ __nv_bfloat16 g_Hbf[(size_t)NMAT * NMAT];
__device__ float g_rowpart[4][NMAT / BN][NMAT];
__device__ unsigned g_bar_cnt = 0;
__device__ unsigned g_bar_gen = 0;

__device__ __forceinline__ uint32_t smem_u32(const void* p) {
    uint32_t a;
    asm("{ .reg .u64 t; cvta.to.shared.u64 t, %1; cvt.u32.u64 %0, t; }" : "=r"(a) : "l"(p));
    return a;
}
#define CP_ASYNC16(dst, src) asm volatile("cp.async.cg.shared.global [%0], [%1], 16;" :: "r"(dst), "l"(src) : "memory")
#define CP_COMMIT()          asm volatile("cp.async.commit_group;" ::: "memory")
#define CP_WAIT2()           asm volatile("cp.async.wait_group 2;" ::: "memory")
#define CP_WAIT0()           asm volatile("cp.async.wait_group 0;" ::: "memory")
#define LDSM_X4(r0, r1, r2, r3, a) \
    asm volatile("ldmatrix.sync.aligned.m8n8.x4.shared.b16 {%0,%1,%2,%3}, [%4];" \
                 : "=r"(r0), "=r"(r1), "=r"(r2), "=r"(r3) : "r"(a))
#define LDSM_X4T(r0, r1, r2, r3, a) \
    asm volatile("ldmatrix.sync.aligned.m8n8.x4.trans.shared.b16 {%0,%1,%2,%3}, [%4];" \
                 : "=r"(r0), "=r"(r1), "=r"(r2), "=r"(r3) : "r"(a))
#define MMA_BF16(c, a, b) \
    asm volatile("mma.sync.aligned.m16n8k16.row.col.f32.bf16.bf16.f32 " \
                 "{%0,%1,%2,%3}, {%4,%5,%6,%7}, {%8,%9}, {%0,%1,%2,%3};" \
                 : "+f"((c)[0]), "+f"((c)[1]), "+f"((c)[2]), "+f"((c)[3]) \
                 : "r"((a)[0]), "r"((a)[1]), "r"((a)[2]), "r"((a)[3]), "r"((b)[0]), "r"((b)[1]))

__device__ __forceinline__ uint32_t swzA(int row, int colb) {
    return (uint32_t)(row * 64 + (colb ^ (((row >> 1) & 3) << 4)));
}
__device__ __forceinline__ uint32_t swzB(int k, int chunk) {
    return (uint32_t)(k * 256 + ((chunk ^ (k & 7)) << 4));
}
__device__ __forceinline__ uint32_t bf2_bits(__nv_bfloat162 v) {
    uint32_t u; memcpy(&u, &v, 4); return u;
}

// Self-resetting grid barrier. All NCTA CTAs are co-resident (1 CTA/SM,
// grid 128 <= 148 SMs), so spinning is deadlock-free. Generation is compared
// against a locally captured value, so monotonic growth across graph replays
// is harmless; the arrival counter is reset by the last arriver BEFORE the
// generation bump (fence-ordered), so state is clean for the next barrier.
__device__ __forceinline__ void grid_barrier() {
    __syncthreads();
    if (threadIdx.x == 0) {
        __threadfence();
        volatile unsigned* genp = &g_bar_gen;
        const unsigned g = *genp;
        const unsigned my = atomicAdd(&g_bar_cnt, 1u);
        if (my == NCTA - 1) {
            *(volatile unsigned*)&g_bar_cnt = 0u;
            __threadfence();
            *genp = g + 1u;
        } else {
            while (*genp == g) {}
        }
        __threadfence();
    }
    __syncthreads();
}

// ---------------- GEMM body (identical mainloop to R11) ----------------
// MODE 0: L = g_Abf ; H = 4D + I -> g_Hbf + row partials
// MODE 1: L = g_Hbf ; out = s_inv[r] * D (fp32), inv computed in prologue
template <int MODE>
__device__ __forceinline__ void gemm_body(float* __restrict__ Cout,
                                          const uint32_t sb,
                                          const int bx, const int by)
{
    __shared__ float s_inv[BM];

    const int tid = threadIdx.x;
    const int lane = tid & 31;
    const int wid = tid >> 5;
    const int warp_m = wid & 3;
    const int warp_n = wid >> 2;
    const int row0 = by * BM;
    const int col0 = bx * BN;

    const __nv_bfloat16* __restrict__ Lop = (MODE == 0) ? g_Abf : g_Hbf;
    const __nv_bfloat16* __restrict__ Rop = g_Abf;   // B = A k-rows, both modes

    uint32_t abase[2];
#pragma unroll
    for (int st = 0; st < 2; st++)
        abase[st] = swzA(warp_m * 64 + (lane & 15), st * 32 + ((lane >> 4) << 4));

    uint32_t bbase[2][2];
    {
        const int m = lane >> 3, r = lane & 7;
#pragma unroll
        for (int st = 0; st < 2; st++)
#pragma unroll
            for (int np = 0; np < 2; np++)
                bbase[st][np] = swzB(st * 16 + ((m & 1) << 3) + r,
                                     warp_n * 4 + np * 2 + (m >> 1));
    }

    auto fill = [&](int kt, int s) {
        const uint32_t ab = sb + s * A_STAGE;
        const uint32_t bb = sb + SMEM_B_OFF + s * B_STAGE;
#pragma unroll
        for (int i = 0; i < 2; i++) {
            const int ch = i * 512 + tid;
            const int row = ch >> 2, c16 = ch & 3;
            CP_ASYNC16(ab + swzA(row, c16 * 16),
                       Lop + (size_t)(row0 + row) * NMAT + kt * BK + c16 * 8);
        }
        {
            const int krow = tid >> 4, c = tid & 15;
            CP_ASYNC16(bb + swzB(krow, c),
                       Rop + (size_t)(kt * BK + krow) * NMAT + col0 + c * 8);
        }
    };

    float acc[4][4][4];
#pragma unroll
    for (int mt = 0; mt < 4; mt++)
#pragma unroll
        for (int nt = 0; nt < 4; nt++)
#pragma unroll
            for (int j = 0; j < 4; j++) acc[mt][nt][j] = 0.f;

    fill(0, 0); CP_COMMIT();
    fill(1, 1); CP_COMMIT();
    fill(2, 2); CP_COMMIT();

    if (MODE == 1 && tid < BM) {
        const int r = row0 + tid;
        float d = 0.f;
#pragma unroll
        for (int h = 0; h < 4; h++)
#pragma unroll
            for (int t = 0; t < NMAT / BN; t++) d += g_rowpart[h][t][r];
        if (d <= 1e-10f) d = 1.f;
        s_inv[tid] = 2.f / d;
    }
    // s_inv visibility: the mainloop's __syncthreads() (KT >= 1) orders it.

    for (int kt = 0; kt < KT; kt++) {
        CP_WAIT2();
        __syncthreads();
        const int s = kt & (STAGES - 1);
        const uint32_t ab = sb + s * A_STAGE;
        const uint32_t bb = sb + SMEM_B_OFF + s * B_STAGE;

        uint32_t a[4][4], b[2][4];

        // ---- step 0 ----
#pragma unroll
        for (int mt = 0; mt < 4; mt++)
            LDSM_X4(a[mt][0], a[mt][1], a[mt][2], a[mt][3], ab + abase[0] + mt * 1024);
#pragma unroll
        for (int np = 0; np < 2; np++)
            LDSM_X4T(b[np][0], b[np][1], b[np][2], b[np][3], bb + bbase[0][np]);

        const int f = kt + 3;
        if (f < KT) fill(f, f & (STAGES - 1));
        CP_COMMIT();

#pragma unroll
        for (int mt = 0; mt < 4; mt++)
#pragma unroll
            for (int nt = 0; nt < 4; nt++) {
                uint32_t bf[2] = {b[nt >> 1][(nt & 1) * 2], b[nt >> 1][(nt & 1) * 2 + 1]};
                MMA_BF16(acc[mt][nt], a[mt], bf);
            }

        // ---- step 1 ----
#pragma unroll
        for (int mt = 0; mt < 4; mt++)
            LDSM_X4(a[mt][0], a[mt][1], a[mt][2], a[mt][3], ab + abase[1] + mt * 1024);
#pragma unroll
        for (int np = 0; np < 2; np++)
            LDSM_X4T(b[np][0], b[np][1], b[np][2], b[np][3], bb + bbase[1][np]);
#pragma unroll
        for (int mt = 0; mt < 4; mt++)
#pragma unroll
            for (int nt = 0; nt < 4; nt++) {
                uint32_t bf[2] = {b[nt >> 1][(nt & 1) * 2], b[nt >> 1][(nt & 1) * 2 + 1]};
                MMA_BF16(acc[mt][nt], a[mt], bf);
            }
    }
    CP_WAIT0();   // drain outstanding cp.async before smem is reused next phase

    // ---------------- epilogue ----------------
#pragma unroll
    for (int mt = 0; mt < 4; mt++) {
        const int rA = row0 + warp_m * 64 + mt * 16 + (lane >> 2);
        const float s0 = (MODE == 0) ? 4.0f : s_inv[rA - row0];
        const float s1 = (MODE == 0) ? 4.0f : s_inv[rA + 8 - row0];
        float rs0 = 0.f, rs1 = 0.f;
#pragma unroll
        for (int nt = 0; nt < 4; nt++) {
            const int c = col0 + warp_n * 32 + nt * 8 + (lane & 3) * 2;
            float v0 = s0 * acc[mt][nt][0];
            float v1 = s0 * acc[mt][nt][1];
            float v2 = s1 * acc[mt][nt][2];
            float v3 = s1 * acc[mt][nt][3];
            if (MODE == 0) {
                if (rA == c)         v0 += 1.0f;
                if (rA == c + 1)     v1 += 1.0f;
                if (rA + 8 == c)     v2 += 1.0f;
                if (rA + 8 == c + 1) v3 += 1.0f;
                rs0 += v0 + v1;
                rs1 += v2 + v3;
                *reinterpret_cast<__nv_bfloat162*>(g_Hbf + (size_t)rA * NMAT + c) =
                    __floats2bfloat162_rn(v0, v1);
                *reinterpret_cast<__nv_bfloat162*>(g_Hbf + (size_t)(rA + 8) * NMAT + c) =
                    __floats2bfloat162_rn(v2, v3);
            } else {
                *reinterpret_cast<float2*>(Cout + (size_t)rA * NMAT + c) = make_float2(v0, v1);
                *reinterpret_cast<float2*>(Cout + (size_t)(rA + 8) * NMAT + c) = make_float2(v2, v3);
            }
        }
        if (MODE == 0) {
            rs0 += __shfl_xor_sync(0xFFFFFFFF, rs0, 1);
            rs0 += __shfl_xor_sync(0xFFFFFFFF, rs0, 2);
            rs1 += __shfl_xor_sync(0xFFFFFFFF, rs1, 1);
            rs1 += __shfl_xor_sync(0xFFFFFFFF, rs1, 2);
            if ((lane & 3) == 0) {
                g_rowpart[warp_n][bx][rA] = rs0;
                g_rowpart[warp_n][bx][rA + 8] = rs1;
            }
        }
    }
}

// ---------------- fused persistent kernel ----------------
__global__ __launch_bounds__(512, 1)
void gtn_fused(const float* __restrict__ A, float* __restrict__ out)
{
    extern __shared__ char dyn_raw[];
    const uint32_t sb = smem_u32(dyn_raw);
    const int bid = blockIdx.x;
    const int tid = threadIdx.x;

    // Phase 0: convert this CTA's 16-row slab of A to bf16 (coalesced).
    {
        const float4* __restrict__ A4 =
            reinterpret_cast<const float4*>(A) + (size_t)bid * 8192;   // 16 rows * 512 f4
        uint2* __restrict__ O2 =
            reinterpret_cast<uint2*>(g_Abf) + (size_t)bid * 8192;
#pragma unroll
        for (int i = 0; i < 16; i++) {
            const int idx = i * 512 + tid;
            const float4 v = A4[idx];
            uint2 o;
            o.x = bf2_bits(__floats2bfloat162_rn(v.x, v.y));
            o.y = bf2_bits(__floats2bfloat162_rn(v.z, v.w));
            O2[idx] = o;
        }
    }
    grid_barrier();                       // g_Abf visible grid-wide

    const int bx = bid & 15, by = bid >> 4;
    gemm_body<0>(out, sb, bx, by);        // H = 4*A@A + I -> g_Hbf + rowparts
    grid_barrier();                       // g_Hbf + g_rowpart visible
    gemm_body<1>(out, sb, bx, by);        // out = diag(2/deg) @ (H @ A)
}

extern "C" void kernel_launch(void* const* d_in, const int* in_sizes, int n_in,
                              void* d_out, int out_size)
{
    const float* A = (const float*)d_in[0];   // weights unused: softmax over singleton == 1
    float* out = (float*)d_out;

    cudaFuncSetAttribute(gtn_fused, cudaFuncAttributeMaxDynamicSharedMemorySize, SMEM_DYN);
    gtn_fused<<<NCTA, 512, SMEM_DYN>>>(A, out);
}